// round 7
// baseline (speedup 1.0000x reference)
#include <cuda_runtime.h>
#include <cuda_fp16.h>
#include <cstdint>

#define NUM_LAYERS 16
#define KS 31
#define HH 1024
#define WW 1024
#define IMW 1054          // 1024 + 31 - 1
#define NC 3
#define TAPS (KS * KS)    // 961
#define TDIM 256
#define XT 16             // x-tiles of 8 px -> 128 px per block
#define SROW 160          // smem pair-row stride (u32), indices 0..157 used
#define NROWS 38          // 8 y-rows + 30 halo

// weights pre-packed as per-lane m16n8k16 f16 A-fragments:
// [c][ky][slice(2)][lane] -> uint4 {a0,a1,a2,a3} (each a f16x2)
__device__ uint4 g_wfrag[NC * KS * 2 * 32];

__device__ __forceinline__ void mma16(float* d, uint32_t a0, uint32_t a1,
                                      uint32_t a2, uint32_t a3,
                                      uint32_t b0, uint32_t b1) {
    asm volatile(
        "mma.sync.aligned.m16n8k16.row.col.f32.f16.f16.f32 "
        "{%0,%1,%2,%3}, {%4,%5,%6,%7}, {%8,%9}, {%0,%1,%2,%3};"
        : "+f"(d[0]), "+f"(d[1]), "+f"(d[2]), "+f"(d[3])
        : "r"(a0), "r"(a1), "r"(a2), "r"(a3), "r"(b0), "r"(b1));
}

__device__ __forceinline__ uint32_t pack_h2(float lo, float hi) {
    __half2 h = __halves2half2(__float2half_rn(lo), __float2half_rn(hi));
    return *(uint32_t*)&h;
}

// Pack weights into m16n8k16 f16 A-fragment order (M=16 layers, K=16 taps/slice).
__global__ void prep_w(const float* __restrict__ w) {
    int i = blockIdx.x * blockDim.x + threadIdx.x;
    if (i >= NC * KS * 2 * 32) return;
    int lane = i & 31;
    int s    = (i >> 5) & 1;
    int ky   = (i >> 6) % KS;
    int c    = i / (KS * 2 * 32);
    int g = lane >> 2, t = lane & 3;
    const float* wc = w + (size_t)c * NUM_LAYERS * TAPS + (size_t)ky * KS;
    auto W = [&](int l, int k) -> float {
        int kx = 16 * s + k;
        return (kx < KS) ? wc[(size_t)l * TAPS + kx] : 0.0f;
    };
    uint4 v;
    v.x = pack_h2(W(g,     2 * t),     W(g,     2 * t + 1));
    v.y = pack_h2(W(g + 8, 2 * t),     W(g + 8, 2 * t + 1));
    v.z = pack_h2(W(g,     2 * t + 8), W(g,     2 * t + 9));
    v.w = pack_h2(W(g + 8, 2 * t + 8), W(g + 8, 2 * t + 9));
    g_wfrag[i] = v;
}

__global__ void __launch_bounds__(TDIM, 2)
blur_mma(const float* __restrict__ img, const int* __restrict__ idxp,
         const float* __restrict__ alpha, float* __restrict__ out)
{
    __shared__ uint32_t pairs[NROWS * SROW];  // overlapping f16x2 pairs {v[i], v[i+1]}
    __shared__ float    dsm[8][16][33];       // per-warp D transpose buffer

    const int c  = blockIdx.z;
    const int x0 = blockIdx.x * 128;
    const int y0 = blockIdx.y * 8;
    const int tid = threadIdx.x, wid = tid >> 5, lane = tid & 31;
    const int g = lane >> 2, t = lane & 3;

    // ---- staging: 4 pair-words per chunk from 5 guarded loads, STS.128 ----
    const float* ims = img + (size_t)c * IMW * IMW + (size_t)y0 * IMW + x0;
    const int rem = IMW - x0;                     // >= 158
    const int minr = rem < 159 ? rem : 159;       // valid col count (cols 0..158)
    for (int q = tid; q < (NROWS * SROW) / 4; q += TDIM) {
        int r  = q / (SROW / 4);
        int c4 = (q - r * (SROW / 4)) * 4;
        const float* rowp = ims + (size_t)r * IMW + c4;
        float f0 = 0.f, f1 = 0.f, f2 = 0.f, f3 = 0.f, f4 = 0.f;
        if (c4 + 4 < minr) {
            f0 = __ldg(rowp);     f1 = __ldg(rowp + 1);
            f2 = __ldg(rowp + 2); f3 = __ldg(rowp + 3);
            f4 = __ldg(rowp + 4);
        } else {
            if (c4     < minr) f0 = __ldg(rowp);
            if (c4 + 1 < minr) f1 = __ldg(rowp + 1);
            if (c4 + 2 < minr) f2 = __ldg(rowp + 2);
            if (c4 + 3 < minr) f3 = __ldg(rowp + 3);
        }
        uint4 wv;
        wv.x = pack_h2(f0, f1); wv.y = pack_h2(f1, f2);
        wv.z = pack_h2(f2, f3); wv.w = pack_h2(f3, f4);
        *(uint4*)(pairs + q * 4) = wv;
    }
    __syncthreads();

    float acc[XT][4];
    #pragma unroll
    for (int xt = 0; xt < XT; ++xt)
        acc[xt][0] = acc[xt][1] = acc[xt][2] = acc[xt][3] = 0.0f;

    const uint4* wf = g_wfrag + (size_t)c * KS * 2 * 32 + lane;
    uint4 A0c = wf[0];            // ky=0 slice 0
    uint4 A1c = wf[32];           // ky=0 slice 1

    for (int ky = 0; ky < KS; ++ky) {
        const uint32_t* rp = pairs + (wid + ky) * SROW + g + 2 * t;
        uint32_t B0[4];

        // ---- pass 0: slice 0, F(xt) = {val(xt), val(xt+1)} ----
        B0[0] = rp[0]; B0[1] = rp[8]; B0[2] = rp[16]; B0[3] = rp[24];
        #pragma unroll
        for (int xt = 0; xt < XT; ++xt) {
            mma16(acc[xt], A0c.x, A0c.y, A0c.z, A0c.w,
                  B0[xt & 3], B0[(xt + 1) & 3]);
            if (xt <= 12) B0[xt & 3] = rp[8 * (xt + 4)];
        }
        if (ky + 1 < KS) A0c = wf[((ky + 1) * 2) * 32];      // hidden under pass 1

        // ---- pass 1: slice 1, F(xt) = {val(xt+2), val(xt+3)} ----
        B0[2] = rp[16]; B0[3] = rp[24]; B0[0] = rp[32]; B0[1] = rp[40];
        #pragma unroll
        for (int xt = 0; xt < XT; ++xt) {
            mma16(acc[xt], A1c.x, A1c.y, A1c.z, A1c.w,
                  B0[(xt + 2) & 3], B0[(xt + 3) & 3]);
            if (xt <= 12) B0[(xt + 2) & 3] = rp[8 * (xt + 6)];
        }
        if (ky + 1 < KS) A1c = wf[((ky + 1) * 2 + 1) * 32];  // hidden under next pass 0
    }

    // ---- epilogue: out[c,y,x] = sum_l D[l,x] * alpha[idx,l,y,x] ----
    const int idx = *idxp;
    const int y = y0 + wid;
    #pragma unroll
    for (int ch = 0; ch < 4; ++ch) {          // 4 chunks of 32 px
        #pragma unroll
        for (int q = 0; q < 4; ++q) {
            int xt = ch * 4 + q;
            int xl = q * 8 + 2 * t;
            dsm[wid][g][xl]         = acc[xt][0];
            dsm[wid][g][xl + 1]     = acc[xt][1];
            dsm[wid][g + 8][xl]     = acc[xt][2];
            dsm[wid][g + 8][xl + 1] = acc[xt][3];
        }
        __syncwarp();
        const int xo = x0 + ch * 32 + lane;
        const float* ap = alpha + (((size_t)idx * NUM_LAYERS) * HH + y) * WW + xo;
        float s = 0.0f;
        #pragma unroll
        for (int l = 0; l < NUM_LAYERS; ++l)
            s += dsm[wid][l][lane] * __ldg(ap + (size_t)l * (HH * WW));
        out[((size_t)c * HH + y) * WW + xo] = s;
        __syncwarp();
    }
}

extern "C" void kernel_launch(void* const* d_in, const int* in_sizes, int n_in,
                              void* d_out, int out_size) {
    const float* img   = (const float*)d_in[0];
    const int*   idxp  = (const int*)d_in[1];
    const float* w     = (const float*)d_in[2];
    const float* alpha = (const float*)d_in[3];
    float*       out   = (float*)d_out;

    prep_w<<<(NC * KS * 2 * 32 + 255) / 256, 256>>>(w);

    dim3 grid(WW / 128, HH / 8, NC);
    blur_mma<<<grid, TDIM>>>(img, idxp, alpha, out);
}